// round 13
// baseline (speedup 1.0000x reference)
#include <cuda_runtime.h>
#include <math.h>

#define V_   10475
#define J_   55
#define B_   512
#define V3_  (V_*3)     // 31425
#define K486 486

#define TV 16   // vertices per block (main kernel)
#define TB 64   // batches per block (= 32 pairs)
#define KT 32   // K-chunk

typedef unsigned long long u64;

__device__ __forceinline__ u64 pack2(float lo, float hi) {
    u64 r;
    asm("mov.b64 %0, {%1, %2};" : "=l"(r) : "r"(__float_as_uint(lo)), "r"(__float_as_uint(hi)));
    return r;
}
__device__ __forceinline__ void unpack2(u64 v, float& lo, float& hi) {
    unsigned int a, b;
    asm("mov.b64 {%0, %1}, %2;" : "=r"(a), "=r"(b) : "l"(v));
    lo = __uint_as_float(a); hi = __uint_as_float(b);
}
__device__ __forceinline__ u64 fma2(u64 a, u64 b, u64 c) {
    u64 d;
    asm("fma.rn.f32x2 %0, %1, %2, %3;" : "=l"(d) : "l"(a), "l"(b), "l"(c));
    return d;
}

// -------- device scratch (no allocations allowed) --------
__device__ __align__(16) float g_vbase[V_*3];
__device__ float g_yoff;
__device__ float g_Jbase[J_*3];
__device__ float g_JE[J_*3*10];
__device__ __align__(16) float g_pf_t[K486*B_];     // transposed pose_feature: [k][b]
__device__ __align__(16) float g_A[B_*J_*12];       // per-joint 3x4 skinning matrices

// ============== Kernel 1: vbase = v_template + shapedirs @ shape ==============
__global__ void k_vbase(const float* __restrict__ vt,
                        const float* __restrict__ shapedirs,
                        const float* __restrict__ shape)
{
    int i = blockIdx.x*256 + threadIdx.x;
    if (i < V3_) {
        float acc = vt[i];
        #pragma unroll
        for (int s = 0; s < 10; s++) acc += shape[s] * shapedirs[i*10 + s];
        g_vbase[i] = acc;
    }
}

// ============== Kernel 2: y offset = -min(v_template[:,1]) ==============
__global__ void k_ymin(const float* __restrict__ vt)
{
    __shared__ float red[1024];
    float m = 1e30f;
    for (int v = threadIdx.x; v < V_; v += 1024) m = fminf(m, vt[v*3 + 1]);
    red[threadIdx.x] = m;
    __syncthreads();
    for (int s = 512; s > 0; s >>= 1) {
        if (threadIdx.x < s) red[threadIdx.x] = fminf(red[threadIdx.x], red[threadIdx.x + s]);
        __syncthreads();
    }
    if (threadIdx.x == 0) g_yoff = -red[0];
}

// ============== Kernel 3: Jbase(j,c) and JE(j,c,e) = JR @ [vbase | exprdirs] ==============
__global__ void k_jreg(const float* __restrict__ JR,
                       const float* __restrict__ exprdirs)
{
    int j = blockIdx.x;
    int tid = threadIdx.x;            // 128 threads
    float acc[33];
    #pragma unroll
    for (int i = 0; i < 33; i++) acc[i] = 0.f;

    for (int v = tid; v < V_; v += 128) {
        float jr = JR[j*V_ + v];
        acc[0] += jr * g_vbase[v*3 + 0];
        acc[1] += jr * g_vbase[v*3 + 1];
        acc[2] += jr * g_vbase[v*3 + 2];
        const float* ed = &exprdirs[v*30];
        #pragma unroll
        for (int i = 0; i < 30; i++) acc[3+i] += jr * ed[i];
    }
    __shared__ float red[4][33];
    int lane = tid & 31, w = tid >> 5;
    #pragma unroll
    for (int i = 0; i < 33; i++) {
        float v = acc[i];
        for (int off = 16; off > 0; off >>= 1) v += __shfl_down_sync(0xffffffffu, v, off);
        if (lane == 0) red[w][i] = v;
    }
    __syncthreads();
    if (tid < 33) {
        float s = red[0][tid] + red[1][tid] + red[2][tid] + red[3][tid];
        if (tid < 3) g_Jbase[j*3 + tid] = s;
        else         g_JE[j*30 + (tid-3)] = s;
    }
}

// ============== Kernel 4: per-batch rodrigues, pose_feature, joints, chain, A ==============
__global__ void k_pose(const float* __restrict__ body,
                       const float* __restrict__ hand,
                       const float* __restrict__ head,
                       const float* __restrict__ pelvis,
                       const float* __restrict__ hand_mean,
                       const float* __restrict__ expression)
{
    int b = blockIdx.x;
    int tid = threadIdx.x;            // 64 threads
    __shared__ float R_s[J_][9];
    __shared__ float jnt[J_][3];

    if (tid < J_) {
        float r0, r1, r2;
        if (tid == 0) {
            r0 = pelvis[b*3+0]; r1 = pelvis[b*3+1]; r2 = pelvis[b*3+2];
        } else if (tid <= 21) {
            int i = tid - 1;
            r0 = body[(b*21+i)*3+0]; r1 = body[(b*21+i)*3+1]; r2 = body[(b*21+i)*3+2];
        } else if (tid <= 24) {
            int i = tid - 22;
            r0 = head[(b*3+i)*3+0]; r1 = head[(b*3+i)*3+1]; r2 = head[(b*3+i)*3+2];
        } else {
            int h = tid - 25;
            r0 = hand[(b*30+h)*3+0] + hand_mean[h*3+0];
            r1 = hand[(b*30+h)*3+1] + hand_mean[h*3+1];
            r2 = hand[(b*30+h)*3+2] + hand_mean[h*3+2];
        }
        float a2  = r0*r0 + r1*r1 + r2*r2 + 1e-12f;
        float ang = sqrtf(a2);
        float inv = 1.0f / ang;
        float kx = r0*inv, ky = r1*inv, kz = r2*inv;
        float s = sinf(ang), c = cosf(ang);
        float t1 = 1.0f - c;
        float R[9];
        R[0] = c + t1*kx*kx;     R[1] = t1*kx*ky - s*kz;  R[2] = t1*kx*kz + s*ky;
        R[3] = t1*kx*ky + s*kz;  R[4] = c + t1*ky*ky;     R[5] = t1*ky*kz - s*kx;
        R[6] = t1*kx*kz - s*ky;  R[7] = t1*ky*kz + s*kx;  R[8] = c + t1*kz*kz;
        #pragma unroll
        for (int i = 0; i < 9; i++) R_s[tid][i] = R[i];
        if (tid >= 1) {
            #pragma unroll
            for (int i = 0; i < 9; i++) {
                float d = (i == 0 || i == 4 || i == 8) ? 1.0f : 0.0f;
                g_pf_t[((tid-1)*9 + i)*B_ + b] = R[i] - d;
            }
        }
        #pragma unroll
        for (int cc = 0; cc < 3; cc++) {
            float acc = g_Jbase[tid*3 + cc];
            #pragma unroll
            for (int e = 0; e < 10; e++)
                acc += expression[b*10 + e] * g_JE[(tid*3 + cc)*10 + e];
            jnt[tid][cc] = acc;
        }
    }
    __syncthreads();

    if (tid < 3) {
        int r = tid;
        float g0 = R_s[0][r*3+0], g1 = R_s[0][r*3+1], g2 = R_s[0][r*3+2], g3 = jnt[0][r];
        g_A[(b*J_ + 0)*12 + r*4 + 0] = g0;
        g_A[(b*J_ + 0)*12 + r*4 + 1] = g1;
        g_A[(b*J_ + 0)*12 + r*4 + 2] = g2;
        g_A[(b*J_ + 0)*12 + r*4 + 3] = g3 - (g0*jnt[0][0] + g1*jnt[0][1] + g2*jnt[0][2]);
        for (int j = 1; j < J_; j++) {
            float t0 = jnt[j][0] - jnt[j-1][0];
            float t1 = jnt[j][1] - jnt[j-1][1];
            float t2 = jnt[j][2] - jnt[j-1][2];
            float n0 = g0*R_s[j][0] + g1*R_s[j][3] + g2*R_s[j][6];
            float n1 = g0*R_s[j][1] + g1*R_s[j][4] + g2*R_s[j][7];
            float n2 = g0*R_s[j][2] + g1*R_s[j][5] + g2*R_s[j][8];
            float n3 = g0*t0 + g1*t1 + g2*t2 + g3;
            g0 = n0; g1 = n1; g2 = n2; g3 = n3;
            g_A[(b*J_ + j)*12 + r*4 + 0] = g0;
            g_A[(b*J_ + j)*12 + r*4 + 1] = g1;
            g_A[(b*J_ + j)*12 + r*4 + 2] = g2;
            g_A[(b*J_ + j)*12 + r*4 + 3] = g3 - (g0*jnt[j][0] + g1*jnt[j][1] + g2*jnt[j][2]);
        }
    }
}

// ============== Kernel 5: fused GEMM + expression + LBS + epilogue, f32x2 packed ==============
// Batch-pair packing: pair pp holds batches (b0+2pp, b0+2pp+1). Thread (vx, by)
// owns vertex vx and pairs {by, by+16} -> tile-local batches {2by,2by+1,2by+32,2by+33}.
__global__ void __launch_bounds__(256, 2)
k_main(const float* __restrict__ posedirs,
       const float* __restrict__ lbsw,
       const float* __restrict__ exprdirs,
       const float* __restrict__ expression,
       const float* __restrict__ gtrans,
       float* __restrict__ out)
{
    // phase-A tiles and phase-C tiles never live at the same time -> union
    __shared__ __align__(16) union {
        struct {
            float2 pf2[32][34];     // [pair][k], padded row (34*8=272B, 16B-aligned rows)
            float4 pd4[KT][TV];     // [k][vertex] = (x,y,z,unused)
        } a;
        float2 A2[8][32][12];       // [jj][pair][q]: lo=even batch, hi=odd batch
    } U;
    __shared__ float  ed_s[TV][30];
    __shared__ float  ex_s[TB][10];
    __shared__ __align__(16) float2 W2_s[TV][56];   // duplicated weights (w,w)
    __shared__ float  vb_s[TV][3];

    const int v0 = blockIdx.x * TV;
    const int b0 = blockIdx.y * TB;
    const int tid = threadIdx.x;
    const int vx = tid & 15;
    const int by = tid >> 4;       // 0..15

    // ---- one-time tile loads ----
    for (int i = tid; i < TV*56; i += 256) {
        int vv = i / 56, j = i % 56;
        float w = 0.f;
        if (j < J_ && v0 + vv < V_) w = lbsw[(v0+vv)*J_ + j];
        W2_s[vv][j] = make_float2(w, w);
    }
    for (int i = tid; i < TV*30; i += 256) {
        int vv = i / 30, e = i % 30;
        ed_s[vv][e] = (v0 + vv < V_) ? exprdirs[(v0+vv)*30 + e] : 0.f;
    }
    for (int i = tid; i < TB*10; i += 256)
        ex_s[i/10][i%10] = expression[(b0 + i/10)*10 + (i%10)];
    for (int i = tid; i < TV*3; i += 256)
        vb_s[i/3][i%3] = (v0 + i/3 < V_) ? g_vbase[(v0 + i/3)*3 + (i%3)] : 0.f;

    // ---- phase A: delta(pair, c) = PF @ posedirs, packed over batch pairs ----
    u64 acc[2][3];
    #pragma unroll
    for (int p = 0; p < 2; p++)
        #pragma unroll
        for (int c = 0; c < 3; c++) acc[p][c] = pack2(0.f, 0.f);

    for (int k0 = 0; k0 < K486; k0 += KT) {
        __syncthreads();
        // pf: [pair][k] float2, read batch-pairs straight out of g_pf_t
        for (int i = tid; i < 32*KT; i += 256) {
            int k = i >> 5, pp = i & 31;
            float2 v = make_float2(0.f, 0.f);
            if (k0 + k < K486)
                v = *reinterpret_cast<const float2*>(&g_pf_t[(k0+k)*B_ + b0 + 2*pp]);
            U.a.pf2[pp][k] = v;
        }
        // pd: [k][vertex] float4 (x,y,z,pad)
        for (int i = tid; i < KT*TV*3; i += 256) {
            int k = i / 48, c = i % 48;
            int vv = c / 3, cc = c % 3;
            int col = v0*3 + c;
            float val = (k0 + k < K486 && col < V3_) ? posedirs[(size_t)(k0+k)*V3_ + col] : 0.f;
            reinterpret_cast<float*>(&U.a.pd4[k][vv])[cc] = val;
        }
        __syncthreads();

        #pragma unroll
        for (int kk = 0; kk < KT; kk += 2) {
            float4 pA = U.a.pd4[kk][vx];
            float4 pB = U.a.pd4[kk+1][vx];
            longlong2 f0 = *reinterpret_cast<const longlong2*>(&U.a.pf2[by][kk]);      // pair by:    k, k+1
            longlong2 f1 = *reinterpret_cast<const longlong2*>(&U.a.pf2[by+16][kk]);   // pair by+16: k, k+1

            u64 P0a = pack2(pA.x, pA.x), P1a = pack2(pA.y, pA.y), P2a = pack2(pA.z, pA.z);
            u64 P0b = pack2(pB.x, pB.x), P1b = pack2(pB.y, pB.y), P2b = pack2(pB.z, pB.z);

            u64 f0a = (u64)f0.x, f0b = (u64)f0.y;
            u64 f1a = (u64)f1.x, f1b = (u64)f1.y;

            acc[0][0] = fma2(f0a, P0a, acc[0][0]);
            acc[0][1] = fma2(f0a, P1a, acc[0][1]);
            acc[0][2] = fma2(f0a, P2a, acc[0][2]);
            acc[1][0] = fma2(f1a, P0a, acc[1][0]);
            acc[1][1] = fma2(f1a, P1a, acc[1][1]);
            acc[1][2] = fma2(f1a, P2a, acc[1][2]);
            acc[0][0] = fma2(f0b, P0b, acc[0][0]);
            acc[0][1] = fma2(f0b, P1b, acc[0][1]);
            acc[0][2] = fma2(f0b, P2b, acc[0][2]);
            acc[1][0] = fma2(f1b, P0b, acc[1][0]);
            acc[1][1] = fma2(f1b, P1b, acc[1][1]);
            acc[1][2] = fma2(f1b, P2b, acc[1][2]);
        }
    }

    // unpack delta: bi -> tile-local batch {2by, 2by+1, 2by+32, 2by+33}
    float d[4][3];
    #pragma unroll
    for (int p = 0; p < 2; p++)
        #pragma unroll
        for (int c = 0; c < 3; c++) {
            float lo, hi;
            unpack2(acc[p][c], lo, hi);
            d[p*2+0][c] = lo; d[p*2+1][c] = hi;
        }

    // ---- phase B: v_posed = vbase + delta + exprdirs . expression ----
    float px[4], py[4], pz[4];
    #pragma unroll
    for (int bi = 0; bi < 4; bi++) {
        int bb = 2*by + (bi >> 1)*32 + (bi & 1);
        float x = vb_s[vx][0] + d[bi][0];
        float y = vb_s[vx][1] + d[bi][1];
        float z = vb_s[vx][2] + d[bi][2];
        #pragma unroll
        for (int e = 0; e < 10; e++) {
            float ex = ex_s[bb][e];
            x += ex * ed_s[vx][e];
            y += ex * ed_s[vx][10+e];
            z += ex * ed_s[vx][20+e];
        }
        px[bi] = x; py[bi] = y; pz[bi] = z;
    }

    // ---- phase C: T = sum_j w_j A_j, packed over batch pairs ----
    u64 t2[2][12];
    #pragma unroll
    for (int p = 0; p < 2; p++)
        #pragma unroll
        for (int q = 0; q < 12; q++) t2[p][q] = pack2(0.f, 0.f);

    for (int j0 = 0; j0 < J_; j0 += 8) {
        __syncthreads();
        // stage A2[jj][pair][q] with batch-pair interleave (lo=even b, hi=odd b)
        for (int i = tid; i < TB*8*3; i += 256) {
            int bb  = i / 24;
            int rem = i % 24;
            int jj  = rem / 3;
            int q4  = rem % 3;
            float4 val = make_float4(0.f, 0.f, 0.f, 0.f);
            if (j0 + jj < J_)
                val = *reinterpret_cast<const float4*>(&g_A[((size_t)(b0+bb)*J_ + (j0+jj))*12 + q4*4]);
            int pp = bb >> 1, h = bb & 1;
            float* dst = reinterpret_cast<float*>(&U.A2[jj][pp][0]);
            dst[(q4*4+0)*2 + h] = val.x;
            dst[(q4*4+1)*2 + h] = val.y;
            dst[(q4*4+2)*2 + h] = val.z;
            dst[(q4*4+3)*2 + h] = val.w;
        }
        __syncthreads();
        #pragma unroll
        for (int jj = 0; jj < 8; jj++) {
            u64 w2 = *reinterpret_cast<const u64*>(&W2_s[vx][j0 + jj]);   // (w,w); zero beyond J_
            #pragma unroll
            for (int p = 0; p < 2; p++) {
                const longlong2* ap = reinterpret_cast<const longlong2*>(&U.A2[jj][by + p*16][0]);
                #pragma unroll
                for (int q4 = 0; q4 < 6; q4++) {
                    longlong2 a = ap[q4];                 // two packed f32x2 values
                    t2[p][2*q4+0] = fma2(w2, (u64)a.x, t2[p][2*q4+0]);
                    t2[p][2*q4+1] = fma2(w2, (u64)a.y, t2[p][2*q4+1]);
                }
            }
        }
    }

    // ---- epilogue ----
    int v = v0 + vx;
    if (v < V_) {
        float yoff = g_yoff;
        #pragma unroll
        for (int p = 0; p < 2; p++) {
            float tq[2][12];
            #pragma unroll
            for (int q = 0; q < 12; q++) {
                float lo, hi;
                unpack2(t2[p][q], lo, hi);
                tq[0][q] = lo; tq[1][q] = hi;
            }
            #pragma unroll
            for (int h = 0; h < 2; h++) {
                int bi = p*2 + h;
                int b = b0 + 2*by + p*32 + h;
                float gx = gtrans[b*3+0], gy = gtrans[b*3+1], gz = gtrans[b*3+2];
                float x = px[bi], y = py[bi], z = pz[bi];
                float ox = tq[h][0]*x + tq[h][1]*y + tq[h][2] *z + tq[h][3]  + gx;
                float oy = tq[h][4]*x + tq[h][5]*y + tq[h][6] *z + tq[h][7]  + yoff + gy;
                float oz = tq[h][8]*x + tq[h][9]*y + tq[h][10]*z + tq[h][11] + gz;
                size_t o = ((size_t)b*V_ + v)*3;
                out[o+0] = ox; out[o+1] = oy; out[o+2] = oz;
            }
        }
    }
}

// ============== launch ==============
extern "C" void kernel_launch(void* const* d_in, const int* in_sizes, int n_in,
                              void* d_out, int out_size)
{
    const float* shape       = (const float*)d_in[0];   // (1,10)
    const float* body_pose   = (const float*)d_in[1];   // (B,21,3)
    const float* hand_pose   = (const float*)d_in[2];   // (B,30,3)
    const float* head_pose   = (const float*)d_in[3];   // (B,3,3)
    const float* expression  = (const float*)d_in[4];   // (B,10)
    const float* pelvis_rot  = (const float*)d_in[5];   // (B,3)
    const float* gtrans      = (const float*)d_in[6];   // (B,3)
    const float* v_template  = (const float*)d_in[7];   // (V,3)
    const float* shapedirs   = (const float*)d_in[8];   // (V,3,10)
    const float* exprdirs    = (const float*)d_in[9];   // (V,3,10)
    const float* posedirs    = (const float*)d_in[10];  // (486, V*3)
    const float* lbs_weights = (const float*)d_in[11];  // (V,J)
    const float* J_regressor = (const float*)d_in[12];  // (J,V)
    const float* hand_mean   = (const float*)d_in[13];  // (2,45)
    float* out = (float*)d_out;

    k_vbase<<<(V3_ + 255)/256, 256>>>(v_template, shapedirs, shape);
    k_ymin<<<1, 1024>>>(v_template);
    k_jreg<<<J_, 128>>>(J_regressor, exprdirs);
    k_pose<<<B_, 64>>>(body_pose, hand_pose, head_pose, pelvis_rot, hand_mean, expression);
    dim3 grid((V_ + TV - 1)/TV, B_/TB);
    k_main<<<grid, 256>>>(posedirs, lbs_weights, exprdirs, expression, gtrans, out);
}

// round 14
// speedup vs baseline: 1.0010x; 1.0010x over previous
#include <cuda_runtime.h>
#include <math.h>

#define V_   10475
#define J_   55
#define B_   512
#define V3_  (V_*3)     // 31425
#define K486 486

#define TV 16   // vertices per block (main kernel)
#define TB 64   // batches per block (= 32 pairs)
#define KT 32   // K-chunk

typedef unsigned long long u64;

__device__ __forceinline__ u64 pack2(float lo, float hi) {
    u64 r;
    asm("mov.b64 %0, {%1, %2};" : "=l"(r) : "r"(__float_as_uint(lo)), "r"(__float_as_uint(hi)));
    return r;
}
__device__ __forceinline__ void unpack2(u64 v, float& lo, float& hi) {
    unsigned int a, b;
    asm("mov.b64 {%0, %1}, %2;" : "=r"(a), "=r"(b) : "l"(v));
    lo = __uint_as_float(a); hi = __uint_as_float(b);
}
__device__ __forceinline__ u64 fma2(u64 a, u64 b, u64 c) {
    u64 d;
    asm("fma.rn.f32x2 %0, %1, %2, %3;" : "=l"(d) : "l"(a), "l"(b), "l"(c));
    return d;
}

// -------- device scratch (no allocations allowed) --------
__device__ __align__(16) float g_vbase[V_*3];
__device__ float g_yoff;
__device__ float g_Jbase[J_*3];
__device__ float g_JE[J_*3*10];
__device__ __align__(16) float g_pf_t[K486*B_];     // transposed pose_feature: [k][b]
__device__ __align__(16) float g_A[B_*J_*12];       // per-joint 3x4 skinning matrices

// ============== Kernel 1: vbase = v_template + shapedirs @ shape ==============
__global__ void k_vbase(const float* __restrict__ vt,
                        const float* __restrict__ shapedirs,
                        const float* __restrict__ shape)
{
    int i = blockIdx.x*256 + threadIdx.x;
    if (i < V3_) {
        float acc = vt[i];
        #pragma unroll
        for (int s = 0; s < 10; s++) acc += shape[s] * shapedirs[i*10 + s];
        g_vbase[i] = acc;
    }
}

// ============== Kernel 2: y offset = -min(v_template[:,1]) ==============
__global__ void k_ymin(const float* __restrict__ vt)
{
    __shared__ float red[1024];
    float m = 1e30f;
    for (int v = threadIdx.x; v < V_; v += 1024) m = fminf(m, vt[v*3 + 1]);
    red[threadIdx.x] = m;
    __syncthreads();
    for (int s = 512; s > 0; s >>= 1) {
        if (threadIdx.x < s) red[threadIdx.x] = fminf(red[threadIdx.x], red[threadIdx.x + s]);
        __syncthreads();
    }
    if (threadIdx.x == 0) g_yoff = -red[0];
}

// ============== Kernel 3: Jbase(j,c) and JE(j,c,e) = JR @ [vbase | exprdirs] ==============
__global__ void k_jreg(const float* __restrict__ JR,
                       const float* __restrict__ exprdirs)
{
    int j = blockIdx.x;
    int tid = threadIdx.x;            // 128 threads
    float acc[33];
    #pragma unroll
    for (int i = 0; i < 33; i++) acc[i] = 0.f;

    for (int v = tid; v < V_; v += 128) {
        float jr = JR[j*V_ + v];
        acc[0] += jr * g_vbase[v*3 + 0];
        acc[1] += jr * g_vbase[v*3 + 1];
        acc[2] += jr * g_vbase[v*3 + 2];
        const float* ed = &exprdirs[v*30];
        #pragma unroll
        for (int i = 0; i < 30; i++) acc[3+i] += jr * ed[i];
    }
    __shared__ float red[4][33];
    int lane = tid & 31, w = tid >> 5;
    #pragma unroll
    for (int i = 0; i < 33; i++) {
        float v = acc[i];
        for (int off = 16; off > 0; off >>= 1) v += __shfl_down_sync(0xffffffffu, v, off);
        if (lane == 0) red[w][i] = v;
    }
    __syncthreads();
    if (tid < 33) {
        float s = red[0][tid] + red[1][tid] + red[2][tid] + red[3][tid];
        if (tid < 3) g_Jbase[j*3 + tid] = s;
        else         g_JE[j*30 + (tid-3)] = s;
    }
}

// ============== Kernel 4: per-batch rodrigues, pose_feature, joints, chain, A ==============
__global__ void k_pose(const float* __restrict__ body,
                       const float* __restrict__ hand,
                       const float* __restrict__ head,
                       const float* __restrict__ pelvis,
                       const float* __restrict__ hand_mean,
                       const float* __restrict__ expression)
{
    int b = blockIdx.x;
    int tid = threadIdx.x;            // 64 threads
    __shared__ float R_s[J_][9];
    __shared__ float jnt[J_][3];

    if (tid < J_) {
        float r0, r1, r2;
        if (tid == 0) {
            r0 = pelvis[b*3+0]; r1 = pelvis[b*3+1]; r2 = pelvis[b*3+2];
        } else if (tid <= 21) {
            int i = tid - 1;
            r0 = body[(b*21+i)*3+0]; r1 = body[(b*21+i)*3+1]; r2 = body[(b*21+i)*3+2];
        } else if (tid <= 24) {
            int i = tid - 22;
            r0 = head[(b*3+i)*3+0]; r1 = head[(b*3+i)*3+1]; r2 = head[(b*3+i)*3+2];
        } else {
            int h = tid - 25;
            r0 = hand[(b*30+h)*3+0] + hand_mean[h*3+0];
            r1 = hand[(b*30+h)*3+1] + hand_mean[h*3+1];
            r2 = hand[(b*30+h)*3+2] + hand_mean[h*3+2];
        }
        float a2  = r0*r0 + r1*r1 + r2*r2 + 1e-12f;
        float ang = sqrtf(a2);
        float inv = 1.0f / ang;
        float kx = r0*inv, ky = r1*inv, kz = r2*inv;
        float s = sinf(ang), c = cosf(ang);
        float t1 = 1.0f - c;
        float R[9];
        R[0] = c + t1*kx*kx;     R[1] = t1*kx*ky - s*kz;  R[2] = t1*kx*kz + s*ky;
        R[3] = t1*kx*ky + s*kz;  R[4] = c + t1*ky*ky;     R[5] = t1*ky*kz - s*kx;
        R[6] = t1*kx*kz - s*ky;  R[7] = t1*ky*kz + s*kx;  R[8] = c + t1*kz*kz;
        #pragma unroll
        for (int i = 0; i < 9; i++) R_s[tid][i] = R[i];
        if (tid >= 1) {
            #pragma unroll
            for (int i = 0; i < 9; i++) {
                float d = (i == 0 || i == 4 || i == 8) ? 1.0f : 0.0f;
                g_pf_t[((tid-1)*9 + i)*B_ + b] = R[i] - d;
            }
        }
        #pragma unroll
        for (int cc = 0; cc < 3; cc++) {
            float acc = g_Jbase[tid*3 + cc];
            #pragma unroll
            for (int e = 0; e < 10; e++)
                acc += expression[b*10 + e] * g_JE[(tid*3 + cc)*10 + e];
            jnt[tid][cc] = acc;
        }
    }
    __syncthreads();

    if (tid < 3) {
        int r = tid;
        float g0 = R_s[0][r*3+0], g1 = R_s[0][r*3+1], g2 = R_s[0][r*3+2], g3 = jnt[0][r];
        g_A[(b*J_ + 0)*12 + r*4 + 0] = g0;
        g_A[(b*J_ + 0)*12 + r*4 + 1] = g1;
        g_A[(b*J_ + 0)*12 + r*4 + 2] = g2;
        g_A[(b*J_ + 0)*12 + r*4 + 3] = g3 - (g0*jnt[0][0] + g1*jnt[0][1] + g2*jnt[0][2]);
        for (int j = 1; j < J_; j++) {
            float t0 = jnt[j][0] - jnt[j-1][0];
            float t1 = jnt[j][1] - jnt[j-1][1];
            float t2 = jnt[j][2] - jnt[j-1][2];
            float n0 = g0*R_s[j][0] + g1*R_s[j][3] + g2*R_s[j][6];
            float n1 = g0*R_s[j][1] + g1*R_s[j][4] + g2*R_s[j][7];
            float n2 = g0*R_s[j][2] + g1*R_s[j][5] + g2*R_s[j][8];
            float n3 = g0*t0 + g1*t1 + g2*t2 + g3;
            g0 = n0; g1 = n1; g2 = n2; g3 = n3;
            g_A[(b*J_ + j)*12 + r*4 + 0] = g0;
            g_A[(b*J_ + j)*12 + r*4 + 1] = g1;
            g_A[(b*J_ + j)*12 + r*4 + 2] = g2;
            g_A[(b*J_ + j)*12 + r*4 + 3] = g3 - (g0*jnt[j][0] + g1*jnt[j][1] + g2*jnt[j][2]);
        }
    }
}

// ============== Kernel 5: fused GEMM + expression + LBS + epilogue, f32x2 packed ==============
// Batch-pair packing: pair pp holds batches (b0+2pp, b0+2pp+1). Thread (vx, by)
// owns vertex vx and pairs {by, by+16} -> tile-local batches {2by,2by+1,2by+32,2by+33}.
__global__ void __launch_bounds__(256, 2)
k_main(const float* __restrict__ posedirs,
       const float* __restrict__ lbsw,
       const float* __restrict__ exprdirs,
       const float* __restrict__ expression,
       const float* __restrict__ gtrans,
       float* __restrict__ out)
{
    // phase-A tiles and phase-C tiles never live at the same time -> union
    __shared__ __align__(16) union {
        struct {
            float2 pf2[32][34];     // [pair][k], padded row (34*8=272B, 16B-aligned rows)
            float4 pd4[KT][TV];     // [k][vertex] = (x,y,z,unused)
        } a;
        float2 A2[8][32][12];       // [jj][pair][q]: lo=even batch, hi=odd batch
    } U;
    __shared__ float  ed_s[TV][30];
    __shared__ float  ex_s[TB][10];
    __shared__ __align__(16) float2 W2_s[TV][56];   // duplicated weights (w,w)
    __shared__ float  vb_s[TV][3];

    const int v0 = blockIdx.x * TV;
    const int b0 = blockIdx.y * TB;
    const int tid = threadIdx.x;
    const int vx = tid & 15;
    const int by = tid >> 4;       // 0..15

    // ---- one-time tile loads ----
    for (int i = tid; i < TV*56; i += 256) {
        int vv = i / 56, j = i % 56;
        float w = 0.f;
        if (j < J_ && v0 + vv < V_) w = lbsw[(v0+vv)*J_ + j];
        W2_s[vv][j] = make_float2(w, w);
    }
    for (int i = tid; i < TV*30; i += 256) {
        int vv = i / 30, e = i % 30;
        ed_s[vv][e] = (v0 + vv < V_) ? exprdirs[(v0+vv)*30 + e] : 0.f;
    }
    for (int i = tid; i < TB*10; i += 256)
        ex_s[i/10][i%10] = expression[(b0 + i/10)*10 + (i%10)];
    for (int i = tid; i < TV*3; i += 256)
        vb_s[i/3][i%3] = (v0 + i/3 < V_) ? g_vbase[(v0 + i/3)*3 + (i%3)] : 0.f;

    // ---- phase A: delta(pair, c) = PF @ posedirs, packed over batch pairs ----
    u64 acc[2][3];
    #pragma unroll
    for (int p = 0; p < 2; p++)
        #pragma unroll
        for (int c = 0; c < 3; c++) acc[p][c] = pack2(0.f, 0.f);

    for (int k0 = 0; k0 < K486; k0 += KT) {
        __syncthreads();
        // pf: [pair][k] float2, read batch-pairs straight out of g_pf_t
        for (int i = tid; i < 32*KT; i += 256) {
            int k = i >> 5, pp = i & 31;
            float2 v = make_float2(0.f, 0.f);
            if (k0 + k < K486)
                v = *reinterpret_cast<const float2*>(&g_pf_t[(k0+k)*B_ + b0 + 2*pp]);
            U.a.pf2[pp][k] = v;
        }
        // pd: [k][vertex] float4 (x,y,z,pad)
        for (int i = tid; i < KT*TV*3; i += 256) {
            int k = i / 48, c = i % 48;
            int vv = c / 3, cc = c % 3;
            int col = v0*3 + c;
            float val = (k0 + k < K486 && col < V3_) ? posedirs[(size_t)(k0+k)*V3_ + col] : 0.f;
            reinterpret_cast<float*>(&U.a.pd4[k][vv])[cc] = val;
        }
        __syncthreads();

        #pragma unroll
        for (int kk = 0; kk < KT; kk += 2) {
            float4 pA = U.a.pd4[kk][vx];
            float4 pB = U.a.pd4[kk+1][vx];
            longlong2 f0 = *reinterpret_cast<const longlong2*>(&U.a.pf2[by][kk]);      // pair by:    k, k+1
            longlong2 f1 = *reinterpret_cast<const longlong2*>(&U.a.pf2[by+16][kk]);   // pair by+16: k, k+1

            u64 P0a = pack2(pA.x, pA.x), P1a = pack2(pA.y, pA.y), P2a = pack2(pA.z, pA.z);
            u64 P0b = pack2(pB.x, pB.x), P1b = pack2(pB.y, pB.y), P2b = pack2(pB.z, pB.z);

            u64 f0a = (u64)f0.x, f0b = (u64)f0.y;
            u64 f1a = (u64)f1.x, f1b = (u64)f1.y;

            acc[0][0] = fma2(f0a, P0a, acc[0][0]);
            acc[0][1] = fma2(f0a, P1a, acc[0][1]);
            acc[0][2] = fma2(f0a, P2a, acc[0][2]);
            acc[1][0] = fma2(f1a, P0a, acc[1][0]);
            acc[1][1] = fma2(f1a, P1a, acc[1][1]);
            acc[1][2] = fma2(f1a, P2a, acc[1][2]);
            acc[0][0] = fma2(f0b, P0b, acc[0][0]);
            acc[0][1] = fma2(f0b, P1b, acc[0][1]);
            acc[0][2] = fma2(f0b, P2b, acc[0][2]);
            acc[1][0] = fma2(f1b, P0b, acc[1][0]);
            acc[1][1] = fma2(f1b, P1b, acc[1][1]);
            acc[1][2] = fma2(f1b, P2b, acc[1][2]);
        }
    }

    // unpack delta: bi -> tile-local batch {2by, 2by+1, 2by+32, 2by+33}
    float d[4][3];
    #pragma unroll
    for (int p = 0; p < 2; p++)
        #pragma unroll
        for (int c = 0; c < 3; c++) {
            float lo, hi;
            unpack2(acc[p][c], lo, hi);
            d[p*2+0][c] = lo; d[p*2+1][c] = hi;
        }

    // ---- phase B: v_posed = vbase + delta + exprdirs . expression ----
    float px[4], py[4], pz[4];
    #pragma unroll
    for (int bi = 0; bi < 4; bi++) {
        int bb = 2*by + (bi >> 1)*32 + (bi & 1);
        float x = vb_s[vx][0] + d[bi][0];
        float y = vb_s[vx][1] + d[bi][1];
        float z = vb_s[vx][2] + d[bi][2];
        #pragma unroll
        for (int e = 0; e < 10; e++) {
            float ex = ex_s[bb][e];
            x += ex * ed_s[vx][e];
            y += ex * ed_s[vx][10+e];
            z += ex * ed_s[vx][20+e];
        }
        px[bi] = x; py[bi] = y; pz[bi] = z;
    }

    // ---- phase C: T = sum_j w_j A_j, packed over batch pairs ----
    u64 t2[2][12];
    #pragma unroll
    for (int p = 0; p < 2; p++)
        #pragma unroll
        for (int q = 0; q < 12; q++) t2[p][q] = pack2(0.f, 0.f);

    for (int j0 = 0; j0 < J_; j0 += 8) {
        __syncthreads();
        // stage A2[jj][pair][q] with batch-pair interleave (lo=even b, hi=odd b)
        for (int i = tid; i < TB*8*3; i += 256) {
            int bb  = i / 24;
            int rem = i % 24;
            int jj  = rem / 3;
            int q4  = rem % 3;
            float4 val = make_float4(0.f, 0.f, 0.f, 0.f);
            if (j0 + jj < J_)
                val = *reinterpret_cast<const float4*>(&g_A[((size_t)(b0+bb)*J_ + (j0+jj))*12 + q4*4]);
            int pp = bb >> 1, h = bb & 1;
            float* dst = reinterpret_cast<float*>(&U.A2[jj][pp][0]);
            dst[(q4*4+0)*2 + h] = val.x;
            dst[(q4*4+1)*2 + h] = val.y;
            dst[(q4*4+2)*2 + h] = val.z;
            dst[(q4*4+3)*2 + h] = val.w;
        }
        __syncthreads();
        #pragma unroll
        for (int jj = 0; jj < 8; jj++) {
            u64 w2 = *reinterpret_cast<const u64*>(&W2_s[vx][j0 + jj]);   // (w,w); zero beyond J_
            #pragma unroll
            for (int p = 0; p < 2; p++) {
                const longlong2* ap = reinterpret_cast<const longlong2*>(&U.A2[jj][by + p*16][0]);
                #pragma unroll
                for (int q4 = 0; q4 < 6; q4++) {
                    longlong2 a = ap[q4];                 // two packed f32x2 values
                    t2[p][2*q4+0] = fma2(w2, (u64)a.x, t2[p][2*q4+0]);
                    t2[p][2*q4+1] = fma2(w2, (u64)a.y, t2[p][2*q4+1]);
                }
            }
        }
    }

    // ---- epilogue ----
    int v = v0 + vx;
    if (v < V_) {
        float yoff = g_yoff;
        #pragma unroll
        for (int p = 0; p < 2; p++) {
            float tq[2][12];
            #pragma unroll
            for (int q = 0; q < 12; q++) {
                float lo, hi;
                unpack2(t2[p][q], lo, hi);
                tq[0][q] = lo; tq[1][q] = hi;
            }
            #pragma unroll
            for (int h = 0; h < 2; h++) {
                int bi = p*2 + h;
                int b = b0 + 2*by + p*32 + h;
                float gx = gtrans[b*3+0], gy = gtrans[b*3+1], gz = gtrans[b*3+2];
                float x = px[bi], y = py[bi], z = pz[bi];
                float ox = tq[h][0]*x + tq[h][1]*y + tq[h][2] *z + tq[h][3]  + gx;
                float oy = tq[h][4]*x + tq[h][5]*y + tq[h][6] *z + tq[h][7]  + yoff + gy;
                float oz = tq[h][8]*x + tq[h][9]*y + tq[h][10]*z + tq[h][11] + gz;
                size_t o = ((size_t)b*V_ + v)*3;
                out[o+0] = ox; out[o+1] = oy; out[o+2] = oz;
            }
        }
    }
}

// ============== launch ==============
extern "C" void kernel_launch(void* const* d_in, const int* in_sizes, int n_in,
                              void* d_out, int out_size)
{
    const float* shape       = (const float*)d_in[0];   // (1,10)
    const float* body_pose   = (const float*)d_in[1];   // (B,21,3)
    const float* hand_pose   = (const float*)d_in[2];   // (B,30,3)
    const float* head_pose   = (const float*)d_in[3];   // (B,3,3)
    const float* expression  = (const float*)d_in[4];   // (B,10)
    const float* pelvis_rot  = (const float*)d_in[5];   // (B,3)
    const float* gtrans      = (const float*)d_in[6];   // (B,3)
    const float* v_template  = (const float*)d_in[7];   // (V,3)
    const float* shapedirs   = (const float*)d_in[8];   // (V,3,10)
    const float* exprdirs    = (const float*)d_in[9];   // (V,3,10)
    const float* posedirs    = (const float*)d_in[10];  // (486, V*3)
    const float* lbs_weights = (const float*)d_in[11];  // (V,J)
    const float* J_regressor = (const float*)d_in[12];  // (J,V)
    const float* hand_mean   = (const float*)d_in[13];  // (2,45)
    float* out = (float*)d_out;

    k_vbase<<<(V3_ + 255)/256, 256>>>(v_template, shapedirs, shape);
    k_ymin<<<1, 1024>>>(v_template);
    k_jreg<<<J_, 128>>>(J_regressor, exprdirs);
    k_pose<<<B_, 64>>>(body_pose, hand_pose, head_pose, pelvis_rot, hand_mean, expression);
    dim3 grid((V_ + TV - 1)/TV, B_/TB);
    k_main<<<grid, 256>>>(posedirs, lbs_weights, exprdirs, expression, gtrans, out);
}

// round 15
// speedup vs baseline: 1.6400x; 1.6383x over previous
#include <cuda_runtime.h>
#include <math.h>

#define V_   10475
#define J_   55
#define B_   512
#define V3_  (V_*3)     // 31425
#define K486 486

#define TV 16   // vertices per block
#define TB 64   // batches per block
#define KT 32   // K-chunk (phase A)
#define JT 8    // J-chunk (phase C)

// -------- device scratch (no allocations allowed) --------
__device__ __align__(16) float g_vbase[V_*3];
__device__ float g_yoff;
__device__ float g_Jbase[J_*3];
__device__ float g_JE[J_*3*10];
__device__ __align__(16) float g_pf_t[K486*B_];     // transposed pose_feature: [k][b]
__device__ __align__(16) float g_A[B_*J_*12];       // per-joint 3x4 skinning matrices

// ============== Kernel 1: vbase = v_template + shapedirs @ shape ==============
__global__ void k_vbase(const float* __restrict__ vt,
                        const float* __restrict__ shapedirs,
                        const float* __restrict__ shape)
{
    int i = blockIdx.x*256 + threadIdx.x;
    if (i < V3_) {
        float acc = vt[i];
        #pragma unroll
        for (int s = 0; s < 10; s++) acc += shape[s] * shapedirs[i*10 + s];
        g_vbase[i] = acc;
    }
}

// ============== Kernel 2: y offset = -min(v_template[:,1]) ==============
__global__ void k_ymin(const float* __restrict__ vt)
{
    __shared__ float red[1024];
    float m = 1e30f;
    for (int v = threadIdx.x; v < V_; v += 1024) m = fminf(m, vt[v*3 + 1]);
    red[threadIdx.x] = m;
    __syncthreads();
    for (int s = 512; s > 0; s >>= 1) {
        if (threadIdx.x < s) red[threadIdx.x] = fminf(red[threadIdx.x], red[threadIdx.x + s]);
        __syncthreads();
    }
    if (threadIdx.x == 0) g_yoff = -red[0];
}

// ============== Kernel 3: Jbase(j,c) and JE(j,c,e) = JR @ [vbase | exprdirs] ==============
__global__ void k_jreg(const float* __restrict__ JR,
                       const float* __restrict__ exprdirs)
{
    int j = blockIdx.x;
    int tid = threadIdx.x;            // 128 threads
    float acc[33];
    #pragma unroll
    for (int i = 0; i < 33; i++) acc[i] = 0.f;

    for (int v = tid; v < V_; v += 128) {
        float jr = JR[j*V_ + v];
        acc[0] += jr * g_vbase[v*3 + 0];
        acc[1] += jr * g_vbase[v*3 + 1];
        acc[2] += jr * g_vbase[v*3 + 2];
        const float* ed = &exprdirs[v*30];
        #pragma unroll
        for (int i = 0; i < 30; i++) acc[3+i] += jr * ed[i];
    }
    __shared__ float red[4][33];
    int lane = tid & 31, w = tid >> 5;
    #pragma unroll
    for (int i = 0; i < 33; i++) {
        float v = acc[i];
        for (int off = 16; off > 0; off >>= 1) v += __shfl_down_sync(0xffffffffu, v, off);
        if (lane == 0) red[w][i] = v;
    }
    __syncthreads();
    if (tid < 33) {
        float s = red[0][tid] + red[1][tid] + red[2][tid] + red[3][tid];
        if (tid < 3) g_Jbase[j*3 + tid] = s;
        else         g_JE[j*30 + (tid-3)] = s;
    }
}

// ============== Kernel 4: per-batch rodrigues, pose_feature, joints, chain, A ==============
__global__ void k_pose(const float* __restrict__ body,
                       const float* __restrict__ hand,
                       const float* __restrict__ head,
                       const float* __restrict__ pelvis,
                       const float* __restrict__ hand_mean,
                       const float* __restrict__ expression)
{
    int b = blockIdx.x;
    int tid = threadIdx.x;            // 64 threads
    __shared__ float R_s[J_][9];
    __shared__ float jnt[J_][3];

    if (tid < J_) {
        float r0, r1, r2;
        if (tid == 0) {
            r0 = pelvis[b*3+0]; r1 = pelvis[b*3+1]; r2 = pelvis[b*3+2];
        } else if (tid <= 21) {
            int i = tid - 1;
            r0 = body[(b*21+i)*3+0]; r1 = body[(b*21+i)*3+1]; r2 = body[(b*21+i)*3+2];
        } else if (tid <= 24) {
            int i = tid - 22;
            r0 = head[(b*3+i)*3+0]; r1 = head[(b*3+i)*3+1]; r2 = head[(b*3+i)*3+2];
        } else {
            int h = tid - 25;
            r0 = hand[(b*30+h)*3+0] + hand_mean[h*3+0];
            r1 = hand[(b*30+h)*3+1] + hand_mean[h*3+1];
            r2 = hand[(b*30+h)*3+2] + hand_mean[h*3+2];
        }
        float a2  = r0*r0 + r1*r1 + r2*r2 + 1e-12f;
        float ang = sqrtf(a2);
        float inv = 1.0f / ang;
        float kx = r0*inv, ky = r1*inv, kz = r2*inv;
        float s = sinf(ang), c = cosf(ang);
        float t1 = 1.0f - c;
        float R[9];
        R[0] = c + t1*kx*kx;     R[1] = t1*kx*ky - s*kz;  R[2] = t1*kx*kz + s*ky;
        R[3] = t1*kx*ky + s*kz;  R[4] = c + t1*ky*ky;     R[5] = t1*ky*kz - s*kx;
        R[6] = t1*kx*kz - s*ky;  R[7] = t1*ky*kz + s*kx;  R[8] = c + t1*kz*kz;
        #pragma unroll
        for (int i = 0; i < 9; i++) R_s[tid][i] = R[i];
        if (tid >= 1) {
            #pragma unroll
            for (int i = 0; i < 9; i++) {
                float d = (i == 0 || i == 4 || i == 8) ? 1.0f : 0.0f;
                g_pf_t[((tid-1)*9 + i)*B_ + b] = R[i] - d;
            }
        }
        #pragma unroll
        for (int cc = 0; cc < 3; cc++) {
            float acc = g_Jbase[tid*3 + cc];
            #pragma unroll
            for (int e = 0; e < 10; e++)
                acc += expression[b*10 + e] * g_JE[(tid*3 + cc)*10 + e];
            jnt[tid][cc] = acc;
        }
    }
    __syncthreads();

    if (tid < 3) {
        int r = tid;
        float g0 = R_s[0][r*3+0], g1 = R_s[0][r*3+1], g2 = R_s[0][r*3+2], g3 = jnt[0][r];
        g_A[(b*J_ + 0)*12 + r*4 + 0] = g0;
        g_A[(b*J_ + 0)*12 + r*4 + 1] = g1;
        g_A[(b*J_ + 0)*12 + r*4 + 2] = g2;
        g_A[(b*J_ + 0)*12 + r*4 + 3] = g3 - (g0*jnt[0][0] + g1*jnt[0][1] + g2*jnt[0][2]);
        for (int j = 1; j < J_; j++) {
            float t0 = jnt[j][0] - jnt[j-1][0];
            float t1 = jnt[j][1] - jnt[j-1][1];
            float t2 = jnt[j][2] - jnt[j-1][2];
            float n0 = g0*R_s[j][0] + g1*R_s[j][3] + g2*R_s[j][6];
            float n1 = g0*R_s[j][1] + g1*R_s[j][4] + g2*R_s[j][7];
            float n2 = g0*R_s[j][2] + g1*R_s[j][5] + g2*R_s[j][8];
            float n3 = g0*t0 + g1*t1 + g2*t2 + g3;
            g0 = n0; g1 = n1; g2 = n2; g3 = n3;
            g_A[(b*J_ + j)*12 + r*4 + 0] = g0;
            g_A[(b*J_ + j)*12 + r*4 + 1] = g1;
            g_A[(b*J_ + j)*12 + r*4 + 2] = g2;
            g_A[(b*J_ + j)*12 + r*4 + 3] = g3 - (g0*jnt[j][0] + g1*jnt[j][1] + g2*jnt[j][2]);
        }
    }
}

// ============== Kernel 5: fused GEMM + expression + LBS + epilogue ==============
// Phase A mapping: vx = tid&15 (vertex), by = tid>>4 -> batches by*4 .. by*4+3.
// Phase C mapping: bx = tid&3 (vertex group: verts bx*4..bx*4+3), bb = tid>>2 (batch).
// Phase B results handed between mappings via vp_s staging buffer.
__global__ void __launch_bounds__(256, 2)
k_main(const float* __restrict__ posedirs,
       const float* __restrict__ lbsw,
       const float* __restrict__ exprdirs,
       const float* __restrict__ expression,
       const float* __restrict__ gtrans,
       float* __restrict__ out)
{
    __shared__ __align__(16) union TileU {
        struct {
            float  pf[KT][TB];      // 8 KB  [k][batch]
            float4 pd[KT][TV];      // 8 KB  [k][vertex] = (x,y,z,pad)
        } a;
        float A[JT][TB][12];        // 24 KB [jj][batch][row-major 3x4]
    } U;
    __shared__ __align__(16) float vp_s[TB][TV*3];  // 12 KB v_posed [batch][vert*3+c]
    __shared__ __align__(16) float W_s[56][TV];     // 3.5 KB weights transposed [j][vert]
    __shared__ float ed_s[TV][30];
    __shared__ float ex_s[TB][10];
    __shared__ float vb_s[TV][3];

    const int v0 = blockIdx.x * TV;
    const int b0 = blockIdx.y * TB;
    const int tid = threadIdx.x;

    // ---- one-time tile loads ----
    for (int i = tid; i < 56*TV; i += 256) {        // W transposed: [j][v]
        int j = i / TV, vv = i % TV;
        float w = 0.f;
        if (j < J_ && v0 + vv < V_) w = lbsw[(v0+vv)*J_ + j];
        W_s[j][vv] = w;
    }
    for (int i = tid; i < TV*30; i += 256) {
        int vv = i / 30, e = i % 30;
        ed_s[vv][e] = (v0 + vv < V_) ? exprdirs[(v0+vv)*30 + e] : 0.f;
    }
    for (int i = tid; i < TB*10; i += 256)
        ex_s[i/10][i%10] = expression[(b0 + i/10)*10 + (i%10)];
    for (int i = tid; i < TV*3; i += 256)
        vb_s[i/3][i%3] = (v0 + i/3 < V_) ? g_vbase[(v0 + i/3)*3 + (i%3)] : 0.f;

    // ================= PHASE A: delta = PF @ posedirs =================
    const int vx = tid & 15;
    const int by = tid >> 4;          // batches by*4 .. by*4+3

    float d0x=0.f,d0y=0.f,d0z=0.f, d1x=0.f,d1y=0.f,d1z=0.f;
    float d2x=0.f,d2y=0.f,d2z=0.f, d3x=0.f,d3y=0.f,d3z=0.f;

    for (int k0 = 0; k0 < K486; k0 += KT) {
        __syncthreads();
        // fill pf [k][bb]: coalesced rows of 64 from g_pf_t
        #pragma unroll
        for (int i = tid; i < KT*TB; i += 256) {
            int k = i >> 6, bb = i & 63;
            U.a.pf[k][bb] = (k0 + k < K486) ? g_pf_t[(k0+k)*B_ + b0 + bb] : 0.f;
        }
        // fill pd [k][v] float4(x,y,z,-): scalar global loads (rows not 16B aligned)
        #pragma unroll
        for (int i = tid; i < KT*TV*3; i += 256) {
            int k = i / 48, c = i % 48;
            int vv = c / 3, cc = c % 3;
            int col = v0*3 + c;
            float val = (k0 + k < K486 && col < V3_) ? posedirs[(size_t)(k0+k)*V3_ + col] : 0.f;
            reinterpret_cast<float*>(&U.a.pd[k][vv])[cc] = val;
        }
        __syncthreads();

        #pragma unroll 4
        for (int k = 0; k < KT; k++) {
            float4 f = *reinterpret_cast<const float4*>(&U.a.pf[k][by*4]); // 4 batches
            float4 p = U.a.pd[k][vx];                                      // x,y,z
            d0x += f.x*p.x; d0y += f.x*p.y; d0z += f.x*p.z;
            d1x += f.y*p.x; d1y += f.y*p.y; d1z += f.y*p.z;
            d2x += f.z*p.x; d2y += f.z*p.y; d2z += f.z*p.z;
            d3x += f.w*p.x; d3y += f.w*p.y; d3z += f.w*p.z;
        }
    }

    // ================= PHASE B: v_posed -> vp_s =================
    {
        float bx0 = vb_s[vx][0], bx1 = vb_s[vx][1], bx2 = vb_s[vx][2];
        float dx[4] = {d0x,d1x,d2x,d3x};
        float dy[4] = {d0y,d1y,d2y,d3y};
        float dz[4] = {d0z,d1z,d2z,d3z};
        #pragma unroll
        for (int i = 0; i < 4; i++) {
            int bb = by*4 + i;
            float x = bx0 + dx[i];
            float y = bx1 + dy[i];
            float z = bx2 + dz[i];
            #pragma unroll
            for (int e = 0; e < 10; e++) {
                float ex = ex_s[bb][e];
                x += ex * ed_s[vx][e];
                y += ex * ed_s[vx][10+e];
                z += ex * ed_s[vx][20+e];
            }
            vp_s[bb][vx*3+0] = x;
            vp_s[bb][vx*3+1] = y;
            vp_s[bb][vx*3+2] = z;
        }
    }

    // ================= PHASE C: T = sum_j w_j A_j (1 batch x 4 verts) ========
    const int bx = tid & 3;           // vertex group: verts bx*4 .. bx*4+3
    const int bb = tid >> 2;          // batch 0..63

    float t[4][12];
    #pragma unroll
    for (int vv = 0; vv < 4; vv++)
        #pragma unroll
        for (int q = 0; q < 12; q++) t[vv][q] = 0.f;

    for (int j0 = 0; j0 < J_; j0 += JT) {
        __syncthreads();
        // stage A[jj][bb][12] via float4 loads (g_A rows are 48B-multiples -> aligned)
        #pragma unroll
        for (int i = tid; i < TB*JT*3; i += 256) {
            int ab  = i / 24;
            int rem = i % 24;
            int jj  = rem / 3;
            int q4  = rem % 3;
            float4 val = make_float4(0.f, 0.f, 0.f, 0.f);
            if (j0 + jj < J_)
                val = *reinterpret_cast<const float4*>(&g_A[((size_t)(b0+ab)*J_ + (j0+jj))*12 + q4*4]);
            *reinterpret_cast<float4*>(&U.A[jj][ab][q4*4]) = val;
        }
        __syncthreads();
        #pragma unroll
        for (int jj = 0; jj < JT; jj++) {
            int j = j0 + jj;
            float4 w4 = *reinterpret_cast<const float4*>(&W_s[j][bx*4]);  // 4 verts (0 past J_)
            const float4* ap = reinterpret_cast<const float4*>(&U.A[jj][bb][0]);
            float4 a0 = ap[0], a1 = ap[1], a2 = ap[2];
            float wv[4] = {w4.x, w4.y, w4.z, w4.w};
            #pragma unroll
            for (int vv = 0; vv < 4; vv++) {
                float w = wv[vv];
                t[vv][0]  += w*a0.x; t[vv][1]  += w*a0.y; t[vv][2]  += w*a0.z; t[vv][3]  += w*a0.w;
                t[vv][4]  += w*a1.x; t[vv][5]  += w*a1.y; t[vv][6]  += w*a1.z; t[vv][7]  += w*a1.w;
                t[vv][8]  += w*a2.x; t[vv][9]  += w*a2.y; t[vv][10] += w*a2.z; t[vv][11] += w*a2.w;
            }
        }
    }

    // ================= EPILOGUE =================
    {
        int b = b0 + bb;
        float gx = gtrans[b*3+0];
        float gy = gtrans[b*3+1] + g_yoff;
        float gz = gtrans[b*3+2];
        // read this thread's 4 v_posed triplets (48B aligned)
        const float4* vpp = reinterpret_cast<const float4*>(&vp_s[bb][bx*12]);
        float4 q0 = vpp[0], q1 = vpp[1], q2 = vpp[2];
        float vx4[4] = {q0.x, q0.w, q1.z, q2.y};
        float vy4[4] = {q0.y, q1.x, q1.w, q2.z};
        float vz4[4] = {q0.z, q1.y, q2.x, q2.w};
        #pragma unroll
        for (int vv = 0; vv < 4; vv++) {
            int v = v0 + bx*4 + vv;
            if (v < V_) {
                float x = vx4[vv], y = vy4[vv], z = vz4[vv];
                float ox = t[vv][0]*x + t[vv][1]*y + t[vv][2] *z + t[vv][3]  + gx;
                float oy = t[vv][4]*x + t[vv][5]*y + t[vv][6] *z + t[vv][7]  + gy;
                float oz = t[vv][8]*x + t[vv][9]*y + t[vv][10]*z + t[vv][11] + gz;
                size_t o = ((size_t)b*V_ + v)*3;
                out[o+0] = ox; out[o+1] = oy; out[o+2] = oz;
            }
        }
    }
}

// ============== launch ==============
extern "C" void kernel_launch(void* const* d_in, const int* in_sizes, int n_in,
                              void* d_out, int out_size)
{
    const float* shape       = (const float*)d_in[0];   // (1,10)
    const float* body_pose   = (const float*)d_in[1];   // (B,21,3)
    const float* hand_pose   = (const float*)d_in[2];   // (B,30,3)
    const float* head_pose   = (const float*)d_in[3];   // (B,3,3)
    const float* expression  = (const float*)d_in[4];   // (B,10)
    const float* pelvis_rot  = (const float*)d_in[5];   // (B,3)
    const float* gtrans      = (const float*)d_in[6];   // (B,3)
    const float* v_template  = (const float*)d_in[7];   // (V,3)
    const float* shapedirs   = (const float*)d_in[8];   // (V,3,10)
    const float* exprdirs    = (const float*)d_in[9];   // (V,3,10)
    const float* posedirs    = (const float*)d_in[10];  // (486, V*3)
    const float* lbs_weights = (const float*)d_in[11];  // (V,J)
    const float* J_regressor = (const float*)d_in[12];  // (J,V)
    const float* hand_mean   = (const float*)d_in[13];  // (2,45)
    float* out = (float*)d_out;

    k_vbase<<<(V3_ + 255)/256, 256>>>(v_template, shapedirs, shape);
    k_ymin<<<1, 1024>>>(v_template);
    k_jreg<<<J_, 128>>>(J_regressor, exprdirs);
    k_pose<<<B_, 64>>>(body_pose, hand_pose, head_pose, pelvis_rot, hand_mean, expression);
    dim3 grid((V_ + TV - 1)/TV, B_/TB);
    k_main<<<grid, 256>>>(posedirs, lbs_weights, exprdirs, expression, gtrans, out);
}

// round 16
// speedup vs baseline: 1.7342x; 1.0574x over previous
#include <cuda_runtime.h>
#include <math.h>
#include <stdint.h>

#define V_   10475
#define J_   55
#define B_   512
#define V3_  (V_*3)     // 31425
#define K486 486
#define KPAD 512        // 486 real + 1..10 expr rows (486..495) + zeros

#define TV 16   // vertices per block
#define TB 64   // batches per block
#define KT 32   // K-chunk (phase A)
#define JT 8    // J-chunk (phase C)

// -------- device scratch (no allocations allowed) --------
__device__ __align__(16) float g_vbase[V_*3];
__device__ float g_yoff;
__device__ float g_Jbase[J_*3];
__device__ float g_JE[J_*3*10];
__device__ __align__(16) float g_pf[B_*KPAD];       // [b][k] pose_feature + expr rows + zero pad
__device__ __align__(16) float g_A[B_*J_*12];       // per-joint 3x4 skinning matrices

__device__ __forceinline__ void mma_tf32(float* d,
    uint32_t a0, uint32_t a1, uint32_t a2, uint32_t a3,
    uint32_t b0, uint32_t b1)
{
    asm volatile("mma.sync.aligned.m16n8k8.row.col.f32.tf32.tf32.f32 "
        "{%0,%1,%2,%3}, {%4,%5,%6,%7}, {%8,%9}, {%0,%1,%2,%3};\n"
        : "+f"(d[0]), "+f"(d[1]), "+f"(d[2]), "+f"(d[3])
        : "r"(a0), "r"(a1), "r"(a2), "r"(a3), "r"(b0), "r"(b1));
}

// ============== Kernel 1: vbase = v_template + shapedirs @ shape ==============
__global__ void k_vbase(const float* __restrict__ vt,
                        const float* __restrict__ shapedirs,
                        const float* __restrict__ shape)
{
    int i = blockIdx.x*256 + threadIdx.x;
    if (i < V3_) {
        float acc = vt[i];
        #pragma unroll
        for (int s = 0; s < 10; s++) acc += shape[s] * shapedirs[i*10 + s];
        g_vbase[i] = acc;
    }
}

// ============== Kernel 2: y offset = -min(v_template[:,1]) ==============
__global__ void k_ymin(const float* __restrict__ vt)
{
    __shared__ float red[1024];
    float m = 1e30f;
    for (int v = threadIdx.x; v < V_; v += 1024) m = fminf(m, vt[v*3 + 1]);
    red[threadIdx.x] = m;
    __syncthreads();
    for (int s = 512; s > 0; s >>= 1) {
        if (threadIdx.x < s) red[threadIdx.x] = fminf(red[threadIdx.x], red[threadIdx.x + s]);
        __syncthreads();
    }
    if (threadIdx.x == 0) g_yoff = -red[0];
}

// ============== Kernel 3: Jbase(j,c) and JE(j,c,e) = JR @ [vbase | exprdirs] ==============
__global__ void k_jreg(const float* __restrict__ JR,
                       const float* __restrict__ exprdirs)
{
    int j = blockIdx.x;
    int tid = threadIdx.x;            // 128 threads
    float acc[33];
    #pragma unroll
    for (int i = 0; i < 33; i++) acc[i] = 0.f;

    for (int v = tid; v < V_; v += 128) {
        float jr = JR[j*V_ + v];
        acc[0] += jr * g_vbase[v*3 + 0];
        acc[1] += jr * g_vbase[v*3 + 1];
        acc[2] += jr * g_vbase[v*3 + 2];
        const float* ed = &exprdirs[v*30];
        #pragma unroll
        for (int i = 0; i < 30; i++) acc[3+i] += jr * ed[i];
    }
    __shared__ float red[4][33];
    int lane = tid & 31, w = tid >> 5;
    #pragma unroll
    for (int i = 0; i < 33; i++) {
        float v = acc[i];
        for (int off = 16; off > 0; off >>= 1) v += __shfl_down_sync(0xffffffffu, v, off);
        if (lane == 0) red[w][i] = v;
    }
    __syncthreads();
    if (tid < 33) {
        float s = red[0][tid] + red[1][tid] + red[2][tid] + red[3][tid];
        if (tid < 3) g_Jbase[j*3 + tid] = s;
        else         g_JE[j*30 + (tid-3)] = s;
    }
}

// ============== Kernel 4: per-batch rodrigues, pose_feature(+expr rows), chain, A ==============
__global__ void k_pose(const float* __restrict__ body,
                       const float* __restrict__ hand,
                       const float* __restrict__ head,
                       const float* __restrict__ pelvis,
                       const float* __restrict__ hand_mean,
                       const float* __restrict__ expression)
{
    int b = blockIdx.x;
    int tid = threadIdx.x;            // 64 threads
    __shared__ float R_s[J_][9];
    __shared__ float jnt[J_][3];

    // expr rows (k = 486..495) and zero pad (496..511)
    if (tid < 10) g_pf[(size_t)b*KPAD + 486 + tid] = expression[b*10 + tid];
    else if (tid < 26) g_pf[(size_t)b*KPAD + 486 + tid] = 0.f;

    if (tid < J_) {
        float r0, r1, r2;
        if (tid == 0) {
            r0 = pelvis[b*3+0]; r1 = pelvis[b*3+1]; r2 = pelvis[b*3+2];
        } else if (tid <= 21) {
            int i = tid - 1;
            r0 = body[(b*21+i)*3+0]; r1 = body[(b*21+i)*3+1]; r2 = body[(b*21+i)*3+2];
        } else if (tid <= 24) {
            int i = tid - 22;
            r0 = head[(b*3+i)*3+0]; r1 = head[(b*3+i)*3+1]; r2 = head[(b*3+i)*3+2];
        } else {
            int h = tid - 25;
            r0 = hand[(b*30+h)*3+0] + hand_mean[h*3+0];
            r1 = hand[(b*30+h)*3+1] + hand_mean[h*3+1];
            r2 = hand[(b*30+h)*3+2] + hand_mean[h*3+2];
        }
        float a2  = r0*r0 + r1*r1 + r2*r2 + 1e-12f;
        float ang = sqrtf(a2);
        float inv = 1.0f / ang;
        float kx = r0*inv, ky = r1*inv, kz = r2*inv;
        float s = sinf(ang), c = cosf(ang);
        float t1 = 1.0f - c;
        float R[9];
        R[0] = c + t1*kx*kx;     R[1] = t1*kx*ky - s*kz;  R[2] = t1*kx*kz + s*ky;
        R[3] = t1*kx*ky + s*kz;  R[4] = c + t1*ky*ky;     R[5] = t1*ky*kz - s*kx;
        R[6] = t1*kx*kz - s*ky;  R[7] = t1*ky*kz + s*kx;  R[8] = c + t1*kz*kz;
        #pragma unroll
        for (int i = 0; i < 9; i++) R_s[tid][i] = R[i];
        if (tid >= 1) {
            #pragma unroll
            for (int i = 0; i < 9; i++) {
                float d = (i == 0 || i == 4 || i == 8) ? 1.0f : 0.0f;
                g_pf[(size_t)b*KPAD + (tid-1)*9 + i] = R[i] - d;
            }
        }
        #pragma unroll
        for (int cc = 0; cc < 3; cc++) {
            float acc = g_Jbase[tid*3 + cc];
            #pragma unroll
            for (int e = 0; e < 10; e++)
                acc += expression[b*10 + e] * g_JE[(tid*3 + cc)*10 + e];
            jnt[tid][cc] = acc;
        }
    }
    __syncthreads();

    if (tid < 3) {
        int r = tid;
        float g0 = R_s[0][r*3+0], g1 = R_s[0][r*3+1], g2 = R_s[0][r*3+2], g3 = jnt[0][r];
        g_A[(b*J_ + 0)*12 + r*4 + 0] = g0;
        g_A[(b*J_ + 0)*12 + r*4 + 1] = g1;
        g_A[(b*J_ + 0)*12 + r*4 + 2] = g2;
        g_A[(b*J_ + 0)*12 + r*4 + 3] = g3 - (g0*jnt[0][0] + g1*jnt[0][1] + g2*jnt[0][2]);
        for (int j = 1; j < J_; j++) {
            float t0 = jnt[j][0] - jnt[j-1][0];
            float t1 = jnt[j][1] - jnt[j-1][1];
            float t2 = jnt[j][2] - jnt[j-1][2];
            float n0 = g0*R_s[j][0] + g1*R_s[j][3] + g2*R_s[j][6];
            float n1 = g0*R_s[j][1] + g1*R_s[j][4] + g2*R_s[j][7];
            float n2 = g0*R_s[j][2] + g1*R_s[j][5] + g2*R_s[j][8];
            float n3 = g0*t0 + g1*t1 + g2*t2 + g3;
            g0 = n0; g1 = n1; g2 = n2; g3 = n3;
            g_A[(b*J_ + j)*12 + r*4 + 0] = g0;
            g_A[(b*J_ + j)*12 + r*4 + 1] = g1;
            g_A[(b*J_ + j)*12 + r*4 + 2] = g2;
            g_A[(b*J_ + j)*12 + r*4 + 3] = g3 - (g0*jnt[j][0] + g1*jnt[j][1] + g2*jnt[j][2]);
        }
    }
}

// ============== Kernel 5: tf32-MMA GEMM + LBS + epilogue ==============
// Phase A: D[64b][48col] = PF[64][512] @ PD[512][48] via mma.m16n8k8 tf32.
//   8 warps = 4 m-bands x 2 n-halves; 3 n8-tiles per warp.
//   K rows 0..485 = posedirs, 486..495 = expression blendshapes, rest zero.
// Phase C: per-thread 1 batch x 4 verts scalar LBS (unchanged from R15).
__global__ void __launch_bounds__(256, 2)
k_main(const float* __restrict__ posedirs,
       const float* __restrict__ lbsw,
       const float* __restrict__ exprdirs,
       const float* __restrict__ gtrans,
       float* __restrict__ out)
{
    __shared__ __align__(16) union TileU {
        struct {
            float pf[TB][36];       // [b][k] stride 36 -> bank 4g+c, conflict-free frags
            float pd[KT][56];       // [k][col] stride 56 -> bank 24k+n, conflict-free frags
        } a;                        // 16.4 KB
        float A[JT][TB][12];        // 24 KB [jj][batch][row-major 3x4]
    } U;
    __shared__ __align__(16) float vp_s[TB][TV*3];  // 12 KB v_posed-minus-vbase [b][col]
    __shared__ __align__(16) float W_s[56][TV];     // 3.5 KB weights transposed [j][vert]
    __shared__ float vb_s[TV*3];                    // vbase per col

    const int v0 = blockIdx.x * TV;
    const int b0 = blockIdx.y * TB;
    const int tid = threadIdx.x;
    const int lane = tid & 31, warp = tid >> 5;

    // ---- one-time tile loads ----
    for (int i = tid; i < 56*TV; i += 256) {        // W transposed: [j][v]
        int j = i / TV, vv = i % TV;
        float w = 0.f;
        if (j < J_ && v0 + vv < V_) w = lbsw[(v0+vv)*J_ + j];
        W_s[j][vv] = w;
    }
    if (tid < TV*3)
        vb_s[tid] = (v0*3 + tid < V3_) ? g_vbase[v0*3 + tid] : 0.f;

    // ================= PHASE A: tf32 MMA GEMM =================
    const int mband = warp & 3;           // batches mband*16 .. +15
    const int nhalf = warp >> 2;          // cols nhalf*24 .. +23
    const int gr = lane >> 2, gc = lane & 3;

    float acc[3][4];
    #pragma unroll
    for (int t = 0; t < 3; t++)
        #pragma unroll
        for (int q = 0; q < 4; q++) acc[t][q] = 0.f;

    for (int k0 = 0; k0 < KPAD; k0 += KT) {
        __syncthreads();
        // pf fill: [bb][k] from g_pf (coalesced 32-float rows; smem write conflict-free)
        #pragma unroll
        for (int i = tid; i < TB*KT; i += 256) {
            int bb = i >> 5, k = i & 31;
            U.a.pf[bb][k] = g_pf[(size_t)(b0+bb)*KPAD + k0 + k];
        }
        // pd fill: [k][col]; rows 486..495 are expression dirs
        #pragma unroll
        for (int i = tid; i < KT*48; i += 256) {
            int k = i / 48, c = i % 48;
            int kk = k0 + k;
            int col = v0*3 + c;
            float val = 0.f;
            if (col < V3_) {
                if (kk < K486)
                    val = posedirs[(size_t)kk*V3_ + col];
                else if (kk < K486 + 10)
                    val = exprdirs[(v0 + c/3)*30 + (c%3)*10 + (kk - K486)];
            }
            U.a.pd[k][c] = val;
        }
        __syncthreads();

        #pragma unroll
        for (int ks = 0; ks < KT; ks += 8) {
            int rA = mband*16 + gr;
            uint32_t a0 = __float_as_uint(U.a.pf[rA    ][ks + gc]);
            uint32_t a1 = __float_as_uint(U.a.pf[rA + 8][ks + gc]);
            uint32_t a2 = __float_as_uint(U.a.pf[rA    ][ks + gc + 4]);
            uint32_t a3 = __float_as_uint(U.a.pf[rA + 8][ks + gc + 4]);
            #pragma unroll
            for (int t = 0; t < 3; t++) {
                int n = nhalf*24 + t*8 + gr;
                uint32_t b0f = __float_as_uint(U.a.pd[ks + gc    ][n]);
                uint32_t b1f = __float_as_uint(U.a.pd[ks + gc + 4][n]);
                mma_tf32(acc[t], a0, a1, a2, a3, b0f, b1f);
            }
        }
    }

    // write accumulators to vp_s: D[row][2gc..2gc+1] per tile
    {
        int rA = mband*16 + gr;
        #pragma unroll
        for (int t = 0; t < 3; t++) {
            int colb = nhalf*24 + t*8 + 2*gc;
            *reinterpret_cast<float2*>(&vp_s[rA    ][colb]) = make_float2(acc[t][0], acc[t][1]);
            *reinterpret_cast<float2*>(&vp_s[rA + 8][colb]) = make_float2(acc[t][2], acc[t][3]);
        }
    }

    // ================= PHASE C: T = sum_j w_j A_j (1 batch x 4 verts) ========
    const int bx = tid & 3;           // vertex group: verts bx*4 .. bx*4+3
    const int bb = tid >> 2;          // batch 0..63

    float t[4][12];
    #pragma unroll
    for (int vv = 0; vv < 4; vv++)
        #pragma unroll
        for (int q = 0; q < 12; q++) t[vv][q] = 0.f;

    for (int j0 = 0; j0 < J_; j0 += JT) {
        __syncthreads();
        #pragma unroll
        for (int i = tid; i < TB*JT*3; i += 256) {
            int ab  = i / 24;
            int rem = i % 24;
            int jj  = rem / 3;
            int q4  = rem % 3;
            float4 val = make_float4(0.f, 0.f, 0.f, 0.f);
            if (j0 + jj < J_)
                val = *reinterpret_cast<const float4*>(&g_A[((size_t)(b0+ab)*J_ + (j0+jj))*12 + q4*4]);
            *reinterpret_cast<float4*>(&U.A[jj][ab][q4*4]) = val;
        }
        __syncthreads();
        #pragma unroll
        for (int jj = 0; jj < JT; jj++) {
            int j = j0 + jj;
            float4 w4 = *reinterpret_cast<const float4*>(&W_s[j][bx*4]);  // 4 verts (0 past J_)
            const float4* ap = reinterpret_cast<const float4*>(&U.A[jj][bb][0]);
            float4 a0 = ap[0], a1 = ap[1], a2 = ap[2];
            float wv[4] = {w4.x, w4.y, w4.z, w4.w};
            #pragma unroll
            for (int vv = 0; vv < 4; vv++) {
                float w = wv[vv];
                t[vv][0]  += w*a0.x; t[vv][1]  += w*a0.y; t[vv][2]  += w*a0.z; t[vv][3]  += w*a0.w;
                t[vv][4]  += w*a1.x; t[vv][5]  += w*a1.y; t[vv][6]  += w*a1.z; t[vv][7]  += w*a1.w;
                t[vv][8]  += w*a2.x; t[vv][9]  += w*a2.y; t[vv][10] += w*a2.z; t[vv][11] += w*a2.w;
            }
        }
    }

    // ================= EPILOGUE =================
    {
        int b = b0 + bb;
        float gx = gtrans[b*3+0];
        float gy = gtrans[b*3+1] + g_yoff;
        float gz = gtrans[b*3+2];
        const float4* vpp = reinterpret_cast<const float4*>(&vp_s[bb][bx*12]);
        float4 q0 = vpp[0], q1 = vpp[1], q2 = vpp[2];
        float vx4[4] = {q0.x, q0.w, q1.z, q2.y};
        float vy4[4] = {q0.y, q1.x, q1.w, q2.z};
        float vz4[4] = {q0.z, q1.y, q2.x, q2.w};
        #pragma unroll
        for (int vv = 0; vv < 4; vv++) {
            int v = v0 + bx*4 + vv;
            if (v < V_) {
                float x = vx4[vv] + vb_s[(bx*4+vv)*3 + 0];
                float y = vy4[vv] + vb_s[(bx*4+vv)*3 + 1];
                float z = vz4[vv] + vb_s[(bx*4+vv)*3 + 2];
                float ox = t[vv][0]*x + t[vv][1]*y + t[vv][2] *z + t[vv][3]  + gx;
                float oy = t[vv][4]*x + t[vv][5]*y + t[vv][6] *z + t[vv][7]  + gy;
                float oz = t[vv][8]*x + t[vv][9]*y + t[vv][10]*z + t[vv][11] + gz;
                size_t o = ((size_t)b*V_ + v)*3;
                out[o+0] = ox; out[o+1] = oy; out[o+2] = oz;
            }
        }
    }
}

// ============== launch ==============
extern "C" void kernel_launch(void* const* d_in, const int* in_sizes, int n_in,
                              void* d_out, int out_size)
{
    const float* shape       = (const float*)d_in[0];   // (1,10)
    const float* body_pose   = (const float*)d_in[1];   // (B,21,3)
    const float* hand_pose   = (const float*)d_in[2];   // (B,30,3)
    const float* head_pose   = (const float*)d_in[3];   // (B,3,3)
    const float* expression  = (const float*)d_in[4];   // (B,10)
    const float* pelvis_rot  = (const float*)d_in[5];   // (B,3)
    const float* gtrans      = (const float*)d_in[6];   // (B,3)
    const float* v_template  = (const float*)d_in[7];   // (V,3)
    const float* shapedirs   = (const float*)d_in[8];   // (V,3,10)
    const float* exprdirs    = (const float*)d_in[9];   // (V,3,10)
    const float* posedirs    = (const float*)d_in[10];  // (486, V*3)
    const float* lbs_weights = (const float*)d_in[11];  // (V,J)
    const float* J_regressor = (const float*)d_in[12];  // (J,V)
    const float* hand_mean   = (const float*)d_in[13];  // (2,45)
    float* out = (float*)d_out;

    k_vbase<<<(V3_ + 255)/256, 256>>>(v_template, shapedirs, shape);
    k_ymin<<<1, 1024>>>(v_template);
    k_jreg<<<J_, 128>>>(J_regressor, exprdirs);
    k_pose<<<B_, 64>>>(body_pose, hand_pose, head_pose, pelvis_rot, hand_mean, expression);
    dim3 grid((V_ + TV - 1)/TV, B_/TB);
    k_main<<<grid, 256>>>(posedirs, lbs_weights, exprdirs, gtrans, out);
}

// round 17
// speedup vs baseline: 2.2352x; 1.2889x over previous
#include <cuda_runtime.h>
#include <math.h>
#include <stdint.h>

#define V_   10475
#define J_   55
#define B_   512
#define V3_  (V_*3)     // 31425
#define K486 486
#define KPAD 512        // 486 real + 10 expr rows (486..495) + zero pad

#define TV 16   // vertices per block
#define TB 64   // batches per block
#define KT 32   // K-chunk (phase A)
#define JT 8    // J-chunk (phase C)
#define NCHUNK (KPAD/KT)   // 16

// -------- device scratch (no allocations allowed) --------
__device__ __align__(16) float g_vbase[V_*3];
__device__ float g_yoff;
__device__ float g_Jbase[J_*3];
__device__ float g_JE[J_*3*10];
__device__ __align__(16) float g_pf[B_*KPAD];       // [b][k] pose_feature + expr rows + zero pad
__device__ __align__(16) float g_A[B_*J_*12];       // per-joint 3x4 skinning matrices

__device__ __forceinline__ void mma_tf32(float* d,
    uint32_t a0, uint32_t a1, uint32_t a2, uint32_t a3,
    uint32_t b0, uint32_t b1)
{
    asm volatile("mma.sync.aligned.m16n8k8.row.col.f32.tf32.tf32.f32 "
        "{%0,%1,%2,%3}, {%4,%5,%6,%7}, {%8,%9}, {%0,%1,%2,%3};\n"
        : "+f"(d[0]), "+f"(d[1]), "+f"(d[2]), "+f"(d[3])
        : "r"(a0), "r"(a1), "r"(a2), "r"(a3), "r"(b0), "r"(b1));
}

// ============== Kernel 1: vbase = v_template + shapedirs @ shape ==============
__global__ void k_vbase(const float* __restrict__ vt,
                        const float* __restrict__ shapedirs,
                        const float* __restrict__ shape)
{
    int i = blockIdx.x*256 + threadIdx.x;
    if (i < V3_) {
        float acc = vt[i];
        #pragma unroll
        for (int s = 0; s < 10; s++) acc += shape[s] * shapedirs[i*10 + s];
        g_vbase[i] = acc;
    }
}

// ============== Kernel 2: y offset = -min(v_template[:,1]) ==============
__global__ void k_ymin(const float* __restrict__ vt)
{
    __shared__ float red[1024];
    float m = 1e30f;
    for (int v = threadIdx.x; v < V_; v += 1024) m = fminf(m, vt[v*3 + 1]);
    red[threadIdx.x] = m;
    __syncthreads();
    for (int s = 512; s > 0; s >>= 1) {
        if (threadIdx.x < s) red[threadIdx.x] = fminf(red[threadIdx.x], red[threadIdx.x + s]);
        __syncthreads();
    }
    if (threadIdx.x == 0) g_yoff = -red[0];
}

// ============== Kernel 3: Jbase(j,c) and JE(j,c,e) = JR @ [vbase | exprdirs] ==============
__global__ void k_jreg(const float* __restrict__ JR,
                       const float* __restrict__ exprdirs)
{
    int j = blockIdx.x;
    int tid = threadIdx.x;            // 128 threads
    float acc[33];
    #pragma unroll
    for (int i = 0; i < 33; i++) acc[i] = 0.f;

    for (int v = tid; v < V_; v += 128) {
        float jr = JR[j*V_ + v];
        acc[0] += jr * g_vbase[v*3 + 0];
        acc[1] += jr * g_vbase[v*3 + 1];
        acc[2] += jr * g_vbase[v*3 + 2];
        const float* ed = &exprdirs[v*30];
        #pragma unroll
        for (int i = 0; i < 30; i++) acc[3+i] += jr * ed[i];
    }
    __shared__ float red[4][33];
    int lane = tid & 31, w = tid >> 5;
    #pragma unroll
    for (int i = 0; i < 33; i++) {
        float v = acc[i];
        for (int off = 16; off > 0; off >>= 1) v += __shfl_down_sync(0xffffffffu, v, off);
        if (lane == 0) red[w][i] = v;
    }
    __syncthreads();
    if (tid < 33) {
        float s = red[0][tid] + red[1][tid] + red[2][tid] + red[3][tid];
        if (tid < 3) g_Jbase[j*3 + tid] = s;
        else         g_JE[j*30 + (tid-3)] = s;
    }
}

// ============== Kernel 4: per-batch rodrigues, pose_feature(+expr rows), chain, A ==============
__global__ void k_pose(const float* __restrict__ body,
                       const float* __restrict__ hand,
                       const float* __restrict__ head,
                       const float* __restrict__ pelvis,
                       const float* __restrict__ hand_mean,
                       const float* __restrict__ expression)
{
    int b = blockIdx.x;
    int tid = threadIdx.x;            // 64 threads
    __shared__ float R_s[J_][9];
    __shared__ float jnt[J_][3];

    // expr rows (k = 486..495) and zero pad (496..511)
    if (tid < 10) g_pf[(size_t)b*KPAD + 486 + tid] = expression[b*10 + tid];
    else if (tid < 26) g_pf[(size_t)b*KPAD + 486 + tid] = 0.f;

    if (tid < J_) {
        float r0, r1, r2;
        if (tid == 0) {
            r0 = pelvis[b*3+0]; r1 = pelvis[b*3+1]; r2 = pelvis[b*3+2];
        } else if (tid <= 21) {
            int i = tid - 1;
            r0 = body[(b*21+i)*3+0]; r1 = body[(b*21+i)*3+1]; r2 = body[(b*21+i)*3+2];
        } else if (tid <= 24) {
            int i = tid - 22;
            r0 = head[(b*3+i)*3+0]; r1 = head[(b*3+i)*3+1]; r2 = head[(b*3+i)*3+2];
        } else {
            int h = tid - 25;
            r0 = hand[(b*30+h)*3+0] + hand_mean[h*3+0];
            r1 = hand[(b*30+h)*3+1] + hand_mean[h*3+1];
            r2 = hand[(b*30+h)*3+2] + hand_mean[h*3+2];
        }
        float a2  = r0*r0 + r1*r1 + r2*r2 + 1e-12f;
        float ang = sqrtf(a2);
        float inv = 1.0f / ang;
        float kx = r0*inv, ky = r1*inv, kz = r2*inv;
        float s = sinf(ang), c = cosf(ang);
        float t1 = 1.0f - c;
        float R[9];
        R[0] = c + t1*kx*kx;     R[1] = t1*kx*ky - s*kz;  R[2] = t1*kx*kz + s*ky;
        R[3] = t1*kx*ky + s*kz;  R[4] = c + t1*ky*ky;     R[5] = t1*ky*kz - s*kx;
        R[6] = t1*kx*kz - s*ky;  R[7] = t1*ky*kz + s*kx;  R[8] = c + t1*kz*kz;
        #pragma unroll
        for (int i = 0; i < 9; i++) R_s[tid][i] = R[i];
        if (tid >= 1) {
            #pragma unroll
            for (int i = 0; i < 9; i++) {
                float d = (i == 0 || i == 4 || i == 8) ? 1.0f : 0.0f;
                g_pf[(size_t)b*KPAD + (tid-1)*9 + i] = R[i] - d;
            }
        }
        #pragma unroll
        for (int cc = 0; cc < 3; cc++) {
            float acc = g_Jbase[tid*3 + cc];
            #pragma unroll
            for (int e = 0; e < 10; e++)
                acc += expression[b*10 + e] * g_JE[(tid*3 + cc)*10 + e];
            jnt[tid][cc] = acc;
        }
    }
    __syncthreads();

    if (tid < 3) {
        int r = tid;
        float g0 = R_s[0][r*3+0], g1 = R_s[0][r*3+1], g2 = R_s[0][r*3+2], g3 = jnt[0][r];
        g_A[(b*J_ + 0)*12 + r*4 + 0] = g0;
        g_A[(b*J_ + 0)*12 + r*4 + 1] = g1;
        g_A[(b*J_ + 0)*12 + r*4 + 2] = g2;
        g_A[(b*J_ + 0)*12 + r*4 + 3] = g3 - (g0*jnt[0][0] + g1*jnt[0][1] + g2*jnt[0][2]);
        for (int j = 1; j < J_; j++) {
            float t0 = jnt[j][0] - jnt[j-1][0];
            float t1 = jnt[j][1] - jnt[j-1][1];
            float t2 = jnt[j][2] - jnt[j-1][2];
            float n0 = g0*R_s[j][0] + g1*R_s[j][3] + g2*R_s[j][6];
            float n1 = g0*R_s[j][1] + g1*R_s[j][4] + g2*R_s[j][7];
            float n2 = g0*R_s[j][2] + g1*R_s[j][5] + g2*R_s[j][8];
            float n3 = g0*t0 + g1*t1 + g2*t2 + g3;
            g0 = n0; g1 = n1; g2 = n2; g3 = n3;
            g_A[(b*J_ + j)*12 + r*4 + 0] = g0;
            g_A[(b*J_ + j)*12 + r*4 + 1] = g1;
            g_A[(b*J_ + j)*12 + r*4 + 2] = g2;
            g_A[(b*J_ + j)*12 + r*4 + 3] = g3 - (g0*jnt[j][0] + g1*jnt[j][1] + g2*jnt[j][2]);
        }
    }
}

// ============== Kernel 5: tf32-MMA GEMM + LBS + epilogue ==============
// grid = (8 batch-groups, 655 v-tiles): batch-group fast-varying so the 8
// blocks sharing a posedirs column-slice are co-resident -> L2 reuse.
// Phase A fills are register double-buffered to overlap LDG latency with MMA.
__global__ void __launch_bounds__(256, 3)
k_main(const float* __restrict__ posedirs,
       const float* __restrict__ lbsw,
       const float* __restrict__ exprdirs,
       const float* __restrict__ gtrans,
       float* __restrict__ out)
{
    __shared__ __align__(16) union TileU {
        struct {
            float pf[TB][36];       // [b][k] stride 36 -> conflict-free frags
            float pd[KT][56];       // [k][col] stride 56 -> conflict-free frags
        } a;                        // 16.4 KB
        float A[JT][TB][12];        // 24 KB [jj][batch][row-major 3x4]
    } U;
    __shared__ __align__(16) float vp_s[TB][TV*3];  // 12 KB GEMM result [b][col]
    __shared__ __align__(16) float W_s[56][TV];     // 3.5 KB weights transposed [j][vert]
    __shared__ float vb_s[TV*3];                    // vbase per col

    const int b0 = blockIdx.x * TB;
    const int v0 = blockIdx.y * TV;
    const int tid = threadIdx.x;
    const int lane = tid & 31, warp = tid >> 5;

    // ---- one-time tile loads ----
    for (int i = tid; i < 56*TV; i += 256) {        // W transposed: [j][v]
        int j = i / TV, vv = i % TV;
        float w = 0.f;
        if (j < J_ && v0 + vv < V_) w = lbsw[(v0+vv)*J_ + j];
        W_s[j][vv] = w;
    }
    if (tid < TV*3)
        vb_s[tid] = (v0*3 + tid < V3_) ? g_vbase[v0*3 + tid] : 0.f;

    // ================= PHASE A: tf32 MMA GEMM, pipelined fills =================
    const int mband = warp & 3;           // batches mband*16 .. +15
    const int nhalf = warp >> 2;          // cols nhalf*24 .. +23
    const int gr = lane >> 2, gc = lane & 3;

    float acc[3][4];
    #pragma unroll
    for (int t = 0; t < 3; t++)
        #pragma unroll
        for (int q = 0; q < 4; q++) acc[t][q] = 0.f;

    float rpf[8], rpd[6];
    // prologue: load chunk 0
    {
        const int k0 = 0;
        #pragma unroll
        for (int r = 0; r < 8; r++) {
            int i = tid + r*256;
            rpf[r] = g_pf[(size_t)(b0 + (i >> 5))*KPAD + k0 + (i & 31)];
        }
        #pragma unroll
        for (int r = 0; r < 6; r++) {
            int i = tid + r*256;
            int k = i / 48, c = i % 48;
            int col = v0*3 + c;
            float val = 0.f;
            if (col < V3_) {
                int kk = k0 + k;
                if (kk < K486)           val = posedirs[(size_t)kk*V3_ + col];
                else if (kk < K486 + 10) val = exprdirs[(v0 + c/3)*30 + (c%3)*10 + (kk - K486)];
            }
            rpd[r] = val;
        }
    }

    for (int kc = 0; kc < NCHUNK; kc++) {
        // store current chunk's registers to smem
        #pragma unroll
        for (int r = 0; r < 8; r++) {
            int i = tid + r*256;
            U.a.pf[i >> 5][i & 31] = rpf[r];
        }
        #pragma unroll
        for (int r = 0; r < 6; r++) {
            int i = tid + r*256;
            U.a.pd[i / 48][i % 48] = rpd[r];
        }
        __syncthreads();

        // prefetch next chunk while MMA consumes smem
        if (kc + 1 < NCHUNK) {
            const int k0 = (kc + 1) * KT;
            #pragma unroll
            for (int r = 0; r < 8; r++) {
                int i = tid + r*256;
                rpf[r] = g_pf[(size_t)(b0 + (i >> 5))*KPAD + k0 + (i & 31)];
            }
            #pragma unroll
            for (int r = 0; r < 6; r++) {
                int i = tid + r*256;
                int k = i / 48, c = i % 48;
                int col = v0*3 + c;
                float val = 0.f;
                if (col < V3_) {
                    int kk = k0 + k;
                    if (kk < K486)           val = posedirs[(size_t)kk*V3_ + col];
                    else if (kk < K486 + 10) val = exprdirs[(v0 + c/3)*30 + (c%3)*10 + (kk - K486)];
                }
                rpd[r] = val;
            }
        }

        #pragma unroll
        for (int ks = 0; ks < KT; ks += 8) {
            int rA = mband*16 + gr;
            uint32_t a0 = __float_as_uint(U.a.pf[rA    ][ks + gc]);
            uint32_t a1 = __float_as_uint(U.a.pf[rA + 8][ks + gc]);
            uint32_t a2 = __float_as_uint(U.a.pf[rA    ][ks + gc + 4]);
            uint32_t a3 = __float_as_uint(U.a.pf[rA + 8][ks + gc + 4]);
            #pragma unroll
            for (int t = 0; t < 3; t++) {
                int n = nhalf*24 + t*8 + gr;
                uint32_t b0f = __float_as_uint(U.a.pd[ks + gc    ][n]);
                uint32_t b1f = __float_as_uint(U.a.pd[ks + gc + 4][n]);
                mma_tf32(acc[t], a0, a1, a2, a3, b0f, b1f);
            }
        }
        __syncthreads();
    }

    // write accumulators to vp_s: D[row][2gc..2gc+1] per tile
    {
        int rA = mband*16 + gr;
        #pragma unroll
        for (int t = 0; t < 3; t++) {
            int colb = nhalf*24 + t*8 + 2*gc;
            *reinterpret_cast<float2*>(&vp_s[rA    ][colb]) = make_float2(acc[t][0], acc[t][1]);
            *reinterpret_cast<float2*>(&vp_s[rA + 8][colb]) = make_float2(acc[t][2], acc[t][3]);
        }
    }

    // ================= PHASE C: T = sum_j w_j A_j (1 batch x 4 verts) ========
    const int bx = tid & 3;           // vertex group: verts bx*4 .. bx*4+3
    const int bb = tid >> 2;          // batch 0..63

    float t[4][12];
    #pragma unroll
    for (int vv = 0; vv < 4; vv++)
        #pragma unroll
        for (int q = 0; q < 12; q++) t[vv][q] = 0.f;

    for (int j0 = 0; j0 < J_; j0 += JT) {
        __syncthreads();
        #pragma unroll
        for (int i = tid; i < TB*JT*3; i += 256) {
            int ab  = i / 24;
            int rem = i % 24;
            int jj  = rem / 3;
            int q4  = rem % 3;
            float4 val = make_float4(0.f, 0.f, 0.f, 0.f);
            if (j0 + jj < J_)
                val = *reinterpret_cast<const float4*>(&g_A[((size_t)(b0+ab)*J_ + (j0+jj))*12 + q4*4]);
            *reinterpret_cast<float4*>(&U.A[jj][ab][q4*4]) = val;
        }
        __syncthreads();
        #pragma unroll
        for (int jj = 0; jj < JT; jj++) {
            int j = j0 + jj;
            float4 w4 = *reinterpret_cast<const float4*>(&W_s[j][bx*4]);  // 4 verts (0 past J_)
            const float4* ap = reinterpret_cast<const float4*>(&U.A[jj][bb][0]);
            float4 a0 = ap[0], a1 = ap[1], a2 = ap[2];
            float wv[4] = {w4.x, w4.y, w4.z, w4.w};
            #pragma unroll
            for (int vv = 0; vv < 4; vv++) {
                float w = wv[vv];
                t[vv][0]  += w*a0.x; t[vv][1]  += w*a0.y; t[vv][2]  += w*a0.z; t[vv][3]  += w*a0.w;
                t[vv][4]  += w*a1.x; t[vv][5]  += w*a1.y; t[vv][6]  += w*a1.z; t[vv][7]  += w*a1.w;
                t[vv][8]  += w*a2.x; t[vv][9]  += w*a2.y; t[vv][10] += w*a2.z; t[vv][11] += w*a2.w;
            }
        }
    }

    // ================= EPILOGUE =================
    {
        int b = b0 + bb;
        float gx = gtrans[b*3+0];
        float gy = gtrans[b*3+1] + g_yoff;
        float gz = gtrans[b*3+2];
        const float4* vpp = reinterpret_cast<const float4*>(&vp_s[bb][bx*12]);
        float4 q0 = vpp[0], q1 = vpp[1], q2 = vpp[2];
        float vx4[4] = {q0.x, q0.w, q1.z, q2.y};
        float vy4[4] = {q0.y, q1.x, q1.w, q2.z};
        float vz4[4] = {q0.z, q1.y, q2.x, q2.w};
        #pragma unroll
        for (int vv = 0; vv < 4; vv++) {
            int v = v0 + bx*4 + vv;
            if (v < V_) {
                float x = vx4[vv] + vb_s[(bx*4+vv)*3 + 0];
                float y = vy4[vv] + vb_s[(bx*4+vv)*3 + 1];
                float z = vz4[vv] + vb_s[(bx*4+vv)*3 + 2];
                float ox = t[vv][0]*x + t[vv][1]*y + t[vv][2] *z + t[vv][3]  + gx;
                float oy = t[vv][4]*x + t[vv][5]*y + t[vv][6] *z + t[vv][7]  + gy;
                float oz = t[vv][8]*x + t[vv][9]*y + t[vv][10]*z + t[vv][11] + gz;
                size_t o = ((size_t)b*V_ + v)*3;
                out[o+0] = ox; out[o+1] = oy; out[o+2] = oz;
            }
        }
    }
}

// ============== launch ==============
extern "C" void kernel_launch(void* const* d_in, const int* in_sizes, int n_in,
                              void* d_out, int out_size)
{
    const float* shape       = (const float*)d_in[0];   // (1,10)
    const float* body_pose   = (const float*)d_in[1];   // (B,21,3)
    const float* hand_pose   = (const float*)d_in[2];   // (B,30,3)
    const float* head_pose   = (const float*)d_in[3];   // (B,3,3)
    const float* expression  = (const float*)d_in[4];   // (B,10)
    const float* pelvis_rot  = (const float*)d_in[5];   // (B,3)
    const float* gtrans      = (const float*)d_in[6];   // (B,3)
    const float* v_template  = (const float*)d_in[7];   // (V,3)
    const float* shapedirs   = (const float*)d_in[8];   // (V,3,10)
    const float* exprdirs    = (const float*)d_in[9];   // (V,3,10)
    const float* posedirs    = (const float*)d_in[10];  // (486, V*3)
    const float* lbs_weights = (const float*)d_in[11];  // (V,J)
    const float* J_regressor = (const float*)d_in[12];  // (J,V)
    const float* hand_mean   = (const float*)d_in[13];  // (2,45)
    float* out = (float*)d_out;

    k_vbase<<<(V3_ + 255)/256, 256>>>(v_template, shapedirs, shape);
    k_ymin<<<1, 1024>>>(v_template);
    k_jreg<<<J_, 128>>>(J_regressor, exprdirs);
    k_pose<<<B_, 64>>>(body_pose, hand_pose, head_pose, pelvis_rot, hand_mean, expression);
    dim3 grid(B_/TB, (V_ + TV - 1)/TV);
    k_main<<<grid, 256>>>(posedirs, lbs_weights, exprdirs, gtrans, out);
}